// round 15
// baseline (speedup 1.0000x reference)
#include <cuda_runtime.h>
#include <cuda_bf16.h>
#include <cuda_fp16.h>
#include <math.h>
#include <stdint.h>
#include <float.h>

#define B_  2
#define T_  2048
#define HID_ 2048
#define H_  16
#define D_  128
#define BH_ (B_*H_)
#define BT_ (B_*T_)

// ---------------- device scratch ----------------
__device__ float g_ve[BH_ * D_];
__device__ float g_v1535[BH_ * D_];

// fp16 operands
__device__ __align__(16) __half g_Hfh[(size_t)BT_ * HID_];     // hidden fp16
__device__ __align__(16) __half g_Wfh[3][(size_t)HID_ * HID_]; // qkv weights fp16
__device__ __align__(16) __half g_OWfh[(size_t)HID_ * HID_];   // o_w fp16
__device__ __align__(16) __half g_AOfh[(size_t)BT_ * HID_];    // attn out fp16
__device__ __align__(16) __half g_Qh[(size_t)BH_ * T_ * D_];   // fp16 hi
__device__ __align__(16) __half g_Ql[(size_t)BH_ * T_ * D_];   // fp16 lo (abar only)
__device__ __align__(16) __half g_Kh[(size_t)BH_ * T_ * D_];
__device__ __align__(16) __half g_Kl[(size_t)BH_ * T_ * D_];
__device__ __align__(16) __half g_Vth[(size_t)BH_ * D_ * T_];  // Vt[bh][d][k]

// ---------------- PTX helpers (compute_103-safe) ----------------
__device__ __forceinline__ uint32_t smem_u32(const void* p) {
    uint32_t a;
    asm("{ .reg .u64 t; cvta.to.shared.u64 t, %1; cvt.u32.u64 %0, t; }" : "=r"(a) : "l"(p));
    return a;
}
__device__ __forceinline__ void cp_async16(uint32_t dst, const void* src) {
    asm volatile("cp.async.cg.shared.global [%0], [%1], 16;" :: "r"(dst), "l"(src));
}
#define CP_COMMIT() asm volatile("cp.async.commit_group;" ::: "memory")
#define CP_WAIT(N)  asm volatile("cp.async.wait_group %0;" :: "n"(N) : "memory")

#define LDSM_X4(r, addr) \
    asm volatile("ldmatrix.sync.aligned.m8n8.x4.shared.b16 {%0,%1,%2,%3}, [%4];" \
        : "=r"((r)[0]), "=r"((r)[1]), "=r"((r)[2]), "=r"((r)[3]) : "r"(addr))

__device__ __forceinline__ void mma16816_fp(float* c, const uint32_t* a, const uint32_t* b) {
    asm volatile("mma.sync.aligned.m16n8k16.row.col.f32.f16.f16.f32 "
        "{%0,%1,%2,%3}, {%4,%5,%6,%7}, {%8,%9}, {%0,%1,%2,%3};"
        : "+f"(c[0]), "+f"(c[1]), "+f"(c[2]), "+f"(c[3])
        : "r"(a[0]), "r"(a[1]), "r"(a[2]), "r"(a[3]), "r"(b[0]), "r"(b[1]));
}

__device__ __forceinline__ void split2h(float x, __half& h, __half& l) {
    h = __float2half_rn(x);
    l = __float2half_rn(x - __half2float(h));
}
__device__ __forceinline__ uint32_t packh2(float a, float b) {
    __half2 h = __floats2half2_rn(a, b);
    return *reinterpret_cast<uint32_t*>(&h);
}

// Fast exp2 on the fma/alu pipes (no MUFU). Input y <= ~0 (scores - max).
// round-to-int via magic add; deg-4 poly for 2^f on [-0.5,0.5] (max rel err ~6e-5);
// integer exponent injected via bit add. Clamp keeps masked lanes in normal range.
__device__ __forceinline__ float fexp2(float y) {
    y = fmaxf(y, -80.f);
    const float magic = 12582912.f;           // 1.5 * 2^23
    const float t = y + magic;
    const int ti = __float_as_int(t) << 23;   // round(y) shifted into exponent field
    const float f = y - (t - magic);          // f in [-0.5, 0.5]
    float p = 0.00961813f;
    p = fmaf(p, f, 0.05550411f);
    p = fmaf(p, f, 0.24022651f);
    p = fmaf(p, f, 0.69314718f);
    p = fmaf(p, f, 1.0f);
    return __int_as_float(__float_as_int(p) + ti);
}

// ---------------- input conversions: all fp16 single ----------------
__global__ void convert_all(const float* __restrict__ hs,
                            const float* __restrict__ qw, const float* __restrict__ kw,
                            const float* __restrict__ vw, const float* __restrict__ ow)
{
    const int sel = blockIdx.y;
    if (sel > 0 && blockIdx.x >= 4096) return;
    const size_t i = ((size_t)blockIdx.x * blockDim.x + threadIdx.x) * 4;
    const float* s = (sel == 0) ? hs : (sel == 1) ? qw : (sel == 2) ? kw : (sel == 3) ? vw : ow;
    __half* dst = (sel == 0) ? g_Hfh : (sel == 4) ? g_OWfh : g_Wfh[sel - 1];
    const float4 v = *(const float4*)(s + i);
    *(__half2*)(dst + i)     = __floats2half2_rn(v.x, v.y);
    *(__half2*)(dst + i + 2) = __floats2half2_rn(v.z, v.w);
}

// ---------------- mma.sync fp16 GEMM, 3-stage pipeline ----------------
#define GT_TILE  16384
#define GT_STAGE (2 * GT_TILE)
#define GT_SMEM  (3 * GT_STAGE)

template<int MODE>
__global__ void __launch_bounds__(256) gemm_mma(float* __restrict__ C)
{
    extern __shared__ char smem[];
    const uint32_t sbase = smem_u32(smem);
    const int tid = threadIdx.x;
    const int wid = tid >> 5;
    const int lane = tid & 31;

    int wsel = 0, hsel = 0, mloc, nloc;
    if (MODE == 1) {
        wsel = blockIdx.x >> 4;
        hsel = blockIdx.x & 15;
        mloc = blockIdx.y * 128; nloc = hsel * 128;
    } else {
        mloc = blockIdx.y * 128; nloc = blockIdx.x * 128;
    }

    const int part = tid >> 7;
    const int u = tid & 127;
    const char* gsrc;
    if (MODE == 1) gsrc = (part == 0) ? (const char*)g_Hfh : (const char*)g_Wfh[wsel];
    else           gsrc = (part == 0) ? (const char*)g_AOfh : (const char*)g_OWfh;
    const int growbase = (part == 0) ? mloc : nloc;
    const uint32_t tpart = sbase + part * GT_TILE;

    auto load_stage = [&](int c, int s) {
        const int r = u;
        const char* src = gsrc + ((size_t)(growbase + r) * 2048 + c * 64) * 2;
        const uint32_t drow = tpart + s * GT_STAGE + r * 128;
#pragma unroll
        for (int g = 0; g < 8; g++)
            cp_async16(drow + (((g ^ (r & 7)) << 4)), src + g * 16);
    };

    const int wm = wid & 3;
    const int wn = wid >> 2;

    float acc[2][8][4];
#pragma unroll
    for (int a = 0; a < 2; a++)
#pragma unroll
        for (int b = 0; b < 8; b++)
#pragma unroll
            for (int cx = 0; cx < 4; cx++) acc[a][b][cx] = 0.f;

    load_stage(0, 0); CP_COMMIT();
    load_stage(1, 1); CP_COMMIT();

    for (int c = 0; c < 32; ++c) {
        if (c < 31) { CP_WAIT(1); } else { CP_WAIT(0); }
        __syncthreads();
        if (c + 2 < 32) { load_stage(c + 2, (c + 2) % 3); CP_COMMIT(); }

        const uint32_t st = sbase + (c % 3) * GT_STAGE;
#pragma unroll
        for (int ks = 0; ks < 4; ks++) {
            const int lr = lane & 15;
            const int g = ks * 2 + (lane >> 4);

            uint32_t ah[2][4];
#pragma unroll
            for (int mb = 0; mb < 2; mb++) {
                const int r = wm * 32 + mb * 16 + lr;
                const uint32_t off = r * 128 + (((g ^ (r & 7)) << 4));
                LDSM_X4(ah[mb], st + off);
            }
            uint32_t bhf[8][2];
#pragma unroll
            for (int np = 0; np < 4; np++) {
                const int r = wn * 64 + np * 16 + lr;
                const uint32_t off = r * 128 + (((g ^ (r & 7)) << 4));
                uint32_t t4[4];
                LDSM_X4(t4, st + GT_TILE + off);
                bhf[2*np][0] = t4[0]; bhf[2*np][1] = t4[2];
                bhf[2*np+1][0] = t4[1]; bhf[2*np+1][1] = t4[3];
            }
#pragma unroll
            for (int mb = 0; mb < 2; mb++)
#pragma unroll
                for (int nb = 0; nb < 8; nb++)
                    mma16816_fp(acc[mb][nb], ah[mb], bhf[nb]);
        }
    }

    if (MODE == 0) {
#pragma unroll
        for (int mb = 0; mb < 2; mb++)
#pragma unroll
            for (int rh = 0; rh < 2; rh++) {
                const int row = wm * 32 + mb * 16 + rh * 8 + (lane >> 2);
                float* dst = C + (size_t)(mloc + row) * 2048 + nloc;
                const int cbase = wn * 64 + (lane & 3) * 2;
#pragma unroll
                for (int nb = 0; nb < 8; nb++)
                    *(float2*)(dst + cbase + nb * 8) =
                        make_float2(acc[mb][nb][rh * 2], acc[mb][nb][rh * 2 + 1]);
            }
    } else {
        __syncthreads();
        float* stg = (float*)smem;     // [128][132]
#pragma unroll
        for (int mb = 0; mb < 2; mb++)
#pragma unroll
            for (int rh = 0; rh < 2; rh++) {
                const int row = wm * 32 + mb * 16 + rh * 8 + (lane >> 2);
                const int cbase = wn * 64 + (lane & 3) * 2;
#pragma unroll
                for (int nb = 0; nb < 8; nb++) {
                    stg[row * 132 + cbase + nb * 8]     = acc[mb][nb][rh * 2];
                    stg[row * 132 + cbase + nb * 8 + 1] = acc[mb][nb][rh * 2 + 1];
                }
            }
        __syncthreads();

        if (wsel == 2) {
            for (int idx = tid; idx < 128 * 128; idx += 256) {
                const int d = idx >> 7, r = idx & 127;
                const int gr = mloc + r;
                const int bb = gr >> 11, t = gr & 2047;
                const float x = stg[r * 132 + d];
                g_Vth[((size_t)((bb * H_ + hsel) * D_ + d)) * T_ + t] = __float2half_rn(x);
                if (t == 1535) g_v1535[(bb * H_ + hsel) * 128 + d] = x;
            }
        } else {
            __half* Oh = (wsel == 0) ? g_Qh : g_Kh;
            __half* Ol = (wsel == 0) ? g_Ql : g_Kl;
            for (int idx = tid; idx < 128 * 64; idx += 256) {
                const int r = idx >> 6, j = idx & 63;
                const int gr = mloc + r;
                const int bb = gr >> 11, t = gr & 2047;
                const float inv = powf(10000.f, -(float)j * (1.f / 64.f));
                float s, cc;
                sincosf((float)t * inv, &s, &cc);
                const float x1 = stg[r * 132 + j];
                const float x2 = stg[r * 132 + j + 64];
                const float y1 = x1 * cc - x2 * s;
                const float y2 = x2 * cc + x1 * s;
                const size_t base = (((size_t)(bb * H_ + hsel) * T_ + t) << 7);
                __half h, l;
                split2h(y1, h, l); Oh[base + j] = h;      Ol[base + j] = l;
                split2h(y2, h, l); Oh[base + j + 64] = h; Ol[base + j + 64] = l;
            }
        }
    }
}

// ---------------- A_bar softmax + CAM bernoulli -> g_ve (exact expf; mask-critical) ----------------
__device__ __forceinline__ uint32_t rotl32(uint32_t x, int r) { return (x << r) | (x >> (32 - r)); }

__global__ void __launch_bounds__(256) abar_cam()
{
    const int bh = blockIdx.x;
    __shared__ float qrow[128];
    __shared__ float sc[2048];
    __shared__ float red[256];
    __shared__ float maskf;
    const int tid = threadIdx.x;

    const size_t qoff = ((size_t)bh * T_ + (T_ - 1)) * 128;
    if (tid < 128)
        qrow[tid] = __half2float(g_Qh[qoff + tid]) + __half2float(g_Ql[qoff + tid]);
    __syncthreads();

    for (int k = tid; k < 2048; k += 256) {
        const size_t koff = ((size_t)bh * T_ + k) * 128;
        const __half2* kh = (const __half2*)(g_Kh + koff);
        const __half2* kl = (const __half2*)(g_Kl + koff);
        float s = 0.f;
#pragma unroll
        for (int i = 0; i < 64; i++) {
            const float2 a = __half22float2(kh[i]);
            const float2 b = __half22float2(kl[i]);
            s = fmaf(a.x + b.x, qrow[2 * i], s);
            s = fmaf(a.y + b.y, qrow[2 * i + 1], s);
        }
        sc[k] = s * 0.08838834764831845f;
    }
    __syncthreads();

    float m = -FLT_MAX;
    for (int k = tid; k < 2048; k += 256) m = fmaxf(m, sc[k]);
    red[tid] = m; __syncthreads();
    for (int o = 128; o > 0; o >>= 1) { if (tid < o) red[tid] = fmaxf(red[tid], red[tid + o]); __syncthreads(); }
    const float gm = red[0];
    __syncthreads();

    float sum = 0.f;
    for (int k = tid; k < 2048; k += 256) { const float p = expf(sc[k] - gm); sc[k] = p; sum += p; }
    red[tid] = sum; __syncthreads();
    for (int o = 128; o > 0; o >>= 1) { if (tid < o) red[tid] += red[tid + o]; __syncthreads(); }
    const float invs = 1.f / red[0];
    __syncthreads();

    for (int k = tid; k < 2048; k += 256) sc[k] *= invs;
    __syncthreads();

    float ws = 0.f;
    for (int k = 1536 + tid; k < 2048; k += 256) ws += sc[k];
    red[tid] = ws; __syncthreads();
    for (int o = 128; o > 0; o >>= 1) { if (tid < o) red[tid] += red[tid + o]; __syncthreads(); }

    if (tid == 0) {
        const float avg = fmaxf(red[0] * (1.f / 512.f), 1e-6f);
        float p = fminf(fmaxf(sc[1535] / avg, 0.f), 1.f);
        uint32_t x0 = 0u, x1 = (uint32_t)bh;
        const uint32_t k0 = 0u, k1 = 42u, k2 = 0x1BD11BDAu ^ k0 ^ k1;
        x0 += k0; x1 += k1;
#define TF4(a,b,c,d)  x0+=x1; x1=rotl32(x1,a); x1^=x0; \
                      x0+=x1; x1=rotl32(x1,b); x1^=x0; \
                      x0+=x1; x1=rotl32(x1,c); x1^=x0; \
                      x0+=x1; x1=rotl32(x1,d); x1^=x0;
        TF4(13,15,26,6)   x0 += k1; x1 += k2 + 1u;
        TF4(17,29,16,24)  x0 += k2; x1 += k0 + 2u;
        TF4(13,15,26,6)   x0 += k0; x1 += k1 + 3u;
        TF4(17,29,16,24)  x0 += k1; x1 += k2 + 4u;
        TF4(13,15,26,6)   x0 += k2; x1 += k0 + 5u;
#undef TF4
        const uint32_t bits = x0 ^ x1;
        float uu = __uint_as_float((bits >> 9) | 0x3f800000u) - 1.0f;
        uu = fmaxf(uu, 0.f);
        maskf = (uu < p) ? 1.f : 0.f;
    }
    __syncthreads();

    if (tid < 128)
        g_ve[bh * 128 + tid] = g_v1535[bh * 128 + tid] * maskf * (1.f / 512.f);
}

// CAM window update in-place on fp16 Vt
__global__ void vt_update()
{
    const int idx = blockIdx.x * blockDim.x + threadIdx.x;
    const int bh = idx >> 15;
    const int rem = idx & 32767;
    const int d = rem >> 8;
    const int kk = rem & 255;
    const float ve = g_ve[bh * 128 + d];
    __half2* p = (__half2*)(g_Vth + ((size_t)(bh * 128 + d)) * 2048 + 1536) + kk;
    float2 x = __half22float2(*p);
    *p = __floats2half2_rn(x.x + ve, x.y + ve);
}

// ---------------- fused flash attention (fp16 mma, base-2 softmax on fma pipe) ----------------
#define FL_SMEM 131072

__global__ void __launch_bounds__(256) flash_mma()
{
    extern __shared__ char smem[];
    const uint32_t sb = smem_u32(smem);
    const uint32_t QS = sb, KS = sb + 32768, VS = sb + 98304;
    const int tid = threadIdx.x, wid = tid >> 5, lane = tid & 31;
    const int bh = blockIdx.y;
    const int qb = 15 - blockIdx.x;
    const int nkt = qb + 1;

    {
        const int c = tid >> 7, r = tid & 127;
        const char* sp = (const char*)(g_Qh + ((size_t)(bh * 2048 + qb * 128 + r)) * 128 + c * 64);
        const uint32_t drow = QS + c * 16384 + r * 128;
#pragma unroll
        for (int g = 0; g < 8; g++) cp_async16(drow + ((g ^ (r & 7)) << 4), sp + g * 16);
    }
    CP_COMMIT();

    auto loadK = [&](int j, int s) {
        const int c = tid >> 7, r = tid & 127;
        const char* sp = (const char*)(g_Kh + ((size_t)(bh * 2048 + j * 128 + r)) * 128 + c * 64);
        const uint32_t drow = KS + s * 32768 + c * 16384 + r * 128;
#pragma unroll
        for (int g = 0; g < 8; g++) cp_async16(drow + ((g ^ (r & 7)) << 4), sp + g * 16);
    };
    auto loadV = [&](int j) {
        const int c = tid >> 7, r = tid & 127;
        const char* sp = (const char*)(g_Vth + ((size_t)(bh * 128 + r)) * 2048 + j * 128 + c * 64);
        const uint32_t drow = VS + c * 16384 + r * 128;
#pragma unroll
        for (int g = 0; g < 8; g++) cp_async16(drow + ((g ^ (r & 7)) << 4), sp + g * 16);
    };

    loadK(0, 0); CP_COMMIT();
    loadV(0);    CP_COMMIT();

    float oacc[16][4];
#pragma unroll
    for (int nt = 0; nt < 16; nt++)
#pragma unroll
        for (int e = 0; e < 4; e++) oacc[nt][e] = 0.f;
    float m0 = -1e30f, m1 = -1e30f, l0 = 0.f, l1 = 0.f;
    uint32_t pfrag[8][4];

    // base-2 scale: (1/sqrt(128)) * log2(e)
    const float scale2 = 0.12751879523243606f;
    const int lr = lane & 15;
    const int rloc = (lane >> 2);
    const int colloc = (lane & 3) * 2;

    for (int j = 0; j < nkt; j++) {
        const int sK = j & 1;
        CP_WAIT(1);
        __syncthreads();
        if (j + 1 < nkt) { loadK(j + 1, sK ^ 1); CP_COMMIT(); }

        float sacc[16][4];
#pragma unroll
        for (int nt = 0; nt < 16; nt++)
#pragma unroll
            for (int e = 0; e < 4; e++) sacc[nt][e] = 0.f;

        const uint32_t kst = KS + sK * 32768;
#pragma unroll
        for (int ks = 0; ks < 8; ks++) {
            const int chunk = ks >> 2;
            const int g = (ks & 3) * 2 + (lane >> 4);
            const int ar = wid * 16 + lr;
            const uint32_t aoff = ar * 128 + ((g ^ (ar & 7)) << 4);
            uint32_t ah[4];
            LDSM_X4(ah, QS + chunk * 16384 + aoff);
#pragma unroll
            for (int np = 0; np < 8; np++) {
                const int br = np * 16 + lr;
                const uint32_t boff = br * 128 + ((g ^ (br & 7)) << 4);
                uint32_t t4[4];
                LDSM_X4(t4, kst + chunk * 16384 + boff);
                uint32_t b0[2] = { t4[0], t4[2] };
                uint32_t b1[2] = { t4[1], t4[3] };
                mma16816_fp(sacc[2*np],   ah, b0);
                mma16816_fp(sacc[2*np+1], ah, b1);
            }
        }

        const bool diag = (j == qb);
        const int rg0 = wid * 16 + rloc;
#pragma unroll
        for (int nt = 0; nt < 16; nt++) {
            float* s = sacc[nt];
            s[0] *= scale2; s[1] *= scale2; s[2] *= scale2; s[3] *= scale2;
            if (diag) {
                const int cl = nt * 8 + colloc;
                if (cl     > rg0)     s[0] = -1e30f;
                if (cl + 1 > rg0)     s[1] = -1e30f;
                if (cl     > rg0 + 8) s[2] = -1e30f;
                if (cl + 1 > rg0 + 8) s[3] = -1e30f;
            }
        }

        float mx0 = -1e30f, mx1 = -1e30f;
#pragma unroll
        for (int nt = 0; nt < 16; nt++) {
            mx0 = fmaxf(mx0, fmaxf(sacc[nt][0], sacc[nt][1]));
            mx1 = fmaxf(mx1, fmaxf(sacc[nt][2], sacc[nt][3]));
        }
        mx0 = fmaxf(mx0, __shfl_xor_sync(0xffffffffu, mx0, 1));
        mx0 = fmaxf(mx0, __shfl_xor_sync(0xffffffffu, mx0, 2));
        mx1 = fmaxf(mx1, __shfl_xor_sync(0xffffffffu, mx1, 1));
        mx1 = fmaxf(mx1, __shfl_xor_sync(0xffffffffu, mx1, 2));
        const float mn0 = fmaxf(m0, mx0), mn1 = fmaxf(m1, mx1);
        const float cr0 = fexp2(m0 - mn0), cr1 = fexp2(m1 - mn1);
        l0 *= cr0; l1 *= cr1; m0 = mn0; m1 = mn1;
#pragma unroll
        for (int nt = 0; nt < 16; nt++) {
            oacc[nt][0] *= cr0; oacc[nt][1] *= cr0;
            oacc[nt][2] *= cr1; oacc[nt][3] *= cr1;
        }
        float ps0 = 0.f, ps1 = 0.f;
#pragma unroll
        for (int kb = 0; kb < 8; kb++) {
            const float p00 = fexp2(sacc[2*kb][0]   - mn0), p01 = fexp2(sacc[2*kb][1]   - mn0);
            const float p02 = fexp2(sacc[2*kb][2]   - mn1), p03 = fexp2(sacc[2*kb][3]   - mn1);
            const float p10 = fexp2(sacc[2*kb+1][0] - mn0), p11 = fexp2(sacc[2*kb+1][1] - mn0);
            const float p12 = fexp2(sacc[2*kb+1][2] - mn1), p13 = fexp2(sacc[2*kb+1][3] - mn1);
            pfrag[kb][0] = packh2(p00, p01);
            pfrag[kb][1] = packh2(p02, p03);
            pfrag[kb][2] = packh2(p10, p11);
            pfrag[kb][3] = packh2(p12, p13);
            ps0 += p00 + p01 + p10 + p11;
            ps1 += p02 + p03 + p12 + p13;
        }
        ps0 += __shfl_xor_sync(0xffffffffu, ps0, 1);
        ps0 += __shfl_xor_sync(0xffffffffu, ps0, 2);
        ps1 += __shfl_xor_sync(0xffffffffu, ps1, 1);
        ps1 += __shfl_xor_sync(0xffffffffu, ps1, 2);
        l0 += ps0; l1 += ps1;

        if (j + 1 < nkt) { CP_WAIT(1); } else { CP_WAIT(0); }
        __syncthreads();

#pragma unroll
        for (int kb = 0; kb < 8; kb++) {
            const int chunk = kb >> 2;
            const int g = (kb & 3) * 2 + (lane >> 4);
#pragma unroll
            for (int np = 0; np < 8; np++) {
                const int br = np * 16 + lr;
                const uint32_t boff = br * 128 + ((g ^ (br & 7)) << 4);
                uint32_t t4[4];
                LDSM_X4(t4, VS + chunk * 16384 + boff);
                uint32_t b0[2] = { t4[0], t4[2] };
                uint32_t b1[2] = { t4[1], t4[3] };
                mma16816_fp(oacc[2*np],   pfrag[kb], b0);
                mma16816_fp(oacc[2*np+1], pfrag[kb], b1);
            }
        }
        __syncthreads();
        if (j + 1 < nkt) { loadV(j + 1); CP_COMMIT(); }
    }

    // ---- writeout: fp16 AO ----
    const float inv0 = 1.f / l0, inv1 = 1.f / l1;
    const int bb = bh >> 4, hh = bh & 15;
    const int rgg0 = qb * 128 + wid * 16 + rloc;
    const size_t base0 = ((size_t)(bb * 2048 + rgg0)) * 2048 + hh * 128;
    const size_t base1 = base0 + (size_t)8 * 2048;
#pragma unroll
    for (int nt = 0; nt < 16; nt++) {
        const int d = nt * 8 + colloc;
        *(__half2*)(g_AOfh + base0 + d) = __floats2half2_rn(oacc[nt][0] * inv0, oacc[nt][1] * inv0);
        *(__half2*)(g_AOfh + base1 + d) = __floats2half2_rn(oacc[nt][2] * inv1, oacc[nt][3] * inv1);
    }
}

// ---------------- launch ----------------
extern "C" void kernel_launch(void* const* d_in, const int* in_sizes, int n_in,
                              void* d_out, int out_size)
{
    (void)in_sizes; (void)n_in; (void)out_size;
    const float* hidden = (const float*)d_in[0];
    const float* q_w = (const float*)d_in[2];
    const float* k_w = (const float*)d_in[3];
    const float* v_w = (const float*)d_in[4];
    const float* o_w = (const float*)d_in[5];
    float* out = (float*)d_out;

    cudaFuncSetAttribute(gemm_mma<1>, cudaFuncAttributeMaxDynamicSharedMemorySize, GT_SMEM);
    cudaFuncSetAttribute(gemm_mma<0>, cudaFuncAttributeMaxDynamicSharedMemorySize, GT_SMEM);
    cudaFuncSetAttribute(flash_mma, cudaFuncAttributeMaxDynamicSharedMemorySize, FL_SMEM);

    convert_all<<<dim3(8192, 5), 256>>>(hidden, q_w, k_w, v_w, o_w);
    gemm_mma<1><<<dim3(48, 32), 256, GT_SMEM>>>(nullptr);
    abar_cam<<<32, 256>>>();
    vt_update<<<4096, 256>>>();
    flash_mma<<<dim3(16, 32), 256, FL_SMEM>>>();
    gemm_mma<0><<<dim3(16, 32), 256, GT_SMEM>>>(out);
}

// round 16
// speedup vs baseline: 1.0124x; 1.0124x over previous
#include <cuda_runtime.h>
#include <cuda_bf16.h>
#include <cuda_fp16.h>
#include <math.h>
#include <stdint.h>
#include <float.h>

#define B_  2
#define T_  2048
#define HID_ 2048
#define H_  16
#define D_  128
#define BH_ (B_*H_)
#define BT_ (B_*T_)

// ---------------- device scratch ----------------
__device__ float g_ve[BH_ * D_];
__device__ float g_v1535[BH_ * D_];

// fp16 operands
__device__ __align__(16) __half g_Hfh[(size_t)BT_ * HID_];     // hidden fp16
__device__ __align__(16) __half g_Wfh[3][(size_t)HID_ * HID_]; // qkv weights fp16
__device__ __align__(16) __half g_OWfh[(size_t)HID_ * HID_];   // o_w fp16
__device__ __align__(16) __half g_AOfh[(size_t)BT_ * HID_];    // attn out fp16
__device__ __align__(16) __half g_Qh[(size_t)BH_ * T_ * D_];   // fp16 hi
__device__ __align__(16) __half g_Ql[(size_t)BH_ * T_ * D_];   // fp16 lo (abar only)
__device__ __align__(16) __half g_Kh[(size_t)BH_ * T_ * D_];
__device__ __align__(16) __half g_Kl[(size_t)BH_ * T_ * D_];
__device__ __align__(16) __half g_Vth[(size_t)BH_ * D_ * T_];  // Vt[bh][d][k]

// ---------------- PTX helpers (compute_103-safe) ----------------
__device__ __forceinline__ uint32_t smem_u32(const void* p) {
    uint32_t a;
    asm("{ .reg .u64 t; cvta.to.shared.u64 t, %1; cvt.u32.u64 %0, t; }" : "=r"(a) : "l"(p));
    return a;
}
__device__ __forceinline__ void cp_async16(uint32_t dst, const void* src) {
    asm volatile("cp.async.cg.shared.global [%0], [%1], 16;" :: "r"(dst), "l"(src));
}
#define CP_COMMIT() asm volatile("cp.async.commit_group;" ::: "memory")
#define CP_WAIT(N)  asm volatile("cp.async.wait_group %0;" :: "n"(N) : "memory")

#define LDSM_X4(r, addr) \
    asm volatile("ldmatrix.sync.aligned.m8n8.x4.shared.b16 {%0,%1,%2,%3}, [%4];" \
        : "=r"((r)[0]), "=r"((r)[1]), "=r"((r)[2]), "=r"((r)[3]) : "r"(addr))

__device__ __forceinline__ void mma16816_fp(float* c, const uint32_t* a, const uint32_t* b) {
    asm volatile("mma.sync.aligned.m16n8k16.row.col.f32.f16.f16.f32 "
        "{%0,%1,%2,%3}, {%4,%5,%6,%7}, {%8,%9}, {%0,%1,%2,%3};"
        : "+f"(c[0]), "+f"(c[1]), "+f"(c[2]), "+f"(c[3])
        : "r"(a[0]), "r"(a[1]), "r"(a[2]), "r"(a[3]), "r"(b[0]), "r"(b[1]));
}

__device__ __forceinline__ void split2h(float x, __half& h, __half& l) {
    h = __float2half_rn(x);
    l = __float2half_rn(x - __half2float(h));
}
__device__ __forceinline__ uint32_t packh2(float a, float b) {
    __half2 h = __floats2half2_rn(a, b);
    return *reinterpret_cast<uint32_t*>(&h);
}

// ---------------- input conversions: all fp16 single ----------------
__global__ void convert_all(const float* __restrict__ hs,
                            const float* __restrict__ qw, const float* __restrict__ kw,
                            const float* __restrict__ vw, const float* __restrict__ ow)
{
    const int sel = blockIdx.y;
    if (sel > 0 && blockIdx.x >= 4096) return;
    const size_t i = ((size_t)blockIdx.x * blockDim.x + threadIdx.x) * 4;
    const float* s = (sel == 0) ? hs : (sel == 1) ? qw : (sel == 2) ? kw : (sel == 3) ? vw : ow;
    __half* dst = (sel == 0) ? g_Hfh : (sel == 4) ? g_OWfh : g_Wfh[sel - 1];
    const float4 v = *(const float4*)(s + i);
    *(__half2*)(dst + i)     = __floats2half2_rn(v.x, v.y);
    *(__half2*)(dst + i + 2) = __floats2half2_rn(v.z, v.w);
}

// ---------------- mma.sync fp16 GEMM, 3-stage pipeline ----------------
#define GT_TILE  16384
#define GT_STAGE (2 * GT_TILE)
#define GT_SMEM  (3 * GT_STAGE)

template<int MODE>
__global__ void __launch_bounds__(256) gemm_mma(float* __restrict__ C)
{
    extern __shared__ char smem[];
    const uint32_t sbase = smem_u32(smem);
    const int tid = threadIdx.x;
    const int wid = tid >> 5;
    const int lane = tid & 31;

    int wsel = 0, hsel = 0, mloc, nloc;
    if (MODE == 1) {
        wsel = blockIdx.x >> 4;
        hsel = blockIdx.x & 15;
        mloc = blockIdx.y * 128; nloc = hsel * 128;
    } else {
        mloc = blockIdx.y * 128; nloc = blockIdx.x * 128;
    }

    const int part = tid >> 7;
    const int u = tid & 127;
    const char* gsrc;
    if (MODE == 1) gsrc = (part == 0) ? (const char*)g_Hfh : (const char*)g_Wfh[wsel];
    else           gsrc = (part == 0) ? (const char*)g_AOfh : (const char*)g_OWfh;
    const int growbase = (part == 0) ? mloc : nloc;
    const uint32_t tpart = sbase + part * GT_TILE;

    auto load_stage = [&](int c, int s) {
        const int r = u;
        const char* src = gsrc + ((size_t)(growbase + r) * 2048 + c * 64) * 2;
        const uint32_t drow = tpart + s * GT_STAGE + r * 128;
#pragma unroll
        for (int g = 0; g < 8; g++)
            cp_async16(drow + (((g ^ (r & 7)) << 4)), src + g * 16);
    };

    const int wm = wid & 3;
    const int wn = wid >> 2;

    float acc[2][8][4];
#pragma unroll
    for (int a = 0; a < 2; a++)
#pragma unroll
        for (int b = 0; b < 8; b++)
#pragma unroll
            for (int cx = 0; cx < 4; cx++) acc[a][b][cx] = 0.f;

    load_stage(0, 0); CP_COMMIT();
    load_stage(1, 1); CP_COMMIT();

    for (int c = 0; c < 32; ++c) {
        if (c < 31) { CP_WAIT(1); } else { CP_WAIT(0); }
        __syncthreads();
        if (c + 2 < 32) { load_stage(c + 2, (c + 2) % 3); CP_COMMIT(); }

        const uint32_t st = sbase + (c % 3) * GT_STAGE;
#pragma unroll
        for (int ks = 0; ks < 4; ks++) {
            const int lr = lane & 15;
            const int g = ks * 2 + (lane >> 4);

            uint32_t ah[2][4];
#pragma unroll
            for (int mb = 0; mb < 2; mb++) {
                const int r = wm * 32 + mb * 16 + lr;
                const uint32_t off = r * 128 + (((g ^ (r & 7)) << 4));
                LDSM_X4(ah[mb], st + off);
            }
            uint32_t bhf[8][2];
#pragma unroll
            for (int np = 0; np < 4; np++) {
                const int r = wn * 64 + np * 16 + lr;
                const uint32_t off = r * 128 + (((g ^ (r & 7)) << 4));
                uint32_t t4[4];
                LDSM_X4(t4, st + GT_TILE + off);
                bhf[2*np][0] = t4[0]; bhf[2*np][1] = t4[2];
                bhf[2*np+1][0] = t4[1]; bhf[2*np+1][1] = t4[3];
            }
#pragma unroll
            for (int mb = 0; mb < 2; mb++)
#pragma unroll
                for (int nb = 0; nb < 8; nb++)
                    mma16816_fp(acc[mb][nb], ah[mb], bhf[nb]);
        }
    }

    if (MODE == 0) {
#pragma unroll
        for (int mb = 0; mb < 2; mb++)
#pragma unroll
            for (int rh = 0; rh < 2; rh++) {
                const int row = wm * 32 + mb * 16 + rh * 8 + (lane >> 2);
                float* dst = C + (size_t)(mloc + row) * 2048 + nloc;
                const int cbase = wn * 64 + (lane & 3) * 2;
#pragma unroll
                for (int nb = 0; nb < 8; nb++)
                    *(float2*)(dst + cbase + nb * 8) =
                        make_float2(acc[mb][nb][rh * 2], acc[mb][nb][rh * 2 + 1]);
            }
    } else {
        __syncthreads();
        float* stg = (float*)smem;     // [128][132]
#pragma unroll
        for (int mb = 0; mb < 2; mb++)
#pragma unroll
            for (int rh = 0; rh < 2; rh++) {
                const int row = wm * 32 + mb * 16 + rh * 8 + (lane >> 2);
                const int cbase = wn * 64 + (lane & 3) * 2;
#pragma unroll
                for (int nb = 0; nb < 8; nb++) {
                    stg[row * 132 + cbase + nb * 8]     = acc[mb][nb][rh * 2];
                    stg[row * 132 + cbase + nb * 8 + 1] = acc[mb][nb][rh * 2 + 1];
                }
            }
        __syncthreads();

        if (wsel == 2) {
            for (int idx = tid; idx < 128 * 128; idx += 256) {
                const int d = idx >> 7, r = idx & 127;
                const int gr = mloc + r;
                const int bb = gr >> 11, t = gr & 2047;
                const float x = stg[r * 132 + d];
                g_Vth[((size_t)((bb * H_ + hsel) * D_ + d)) * T_ + t] = __float2half_rn(x);
                if (t == 1535) g_v1535[(bb * H_ + hsel) * 128 + d] = x;
            }
        } else {
            __half* Oh = (wsel == 0) ? g_Qh : g_Kh;
            __half* Ol = (wsel == 0) ? g_Ql : g_Kl;
            for (int idx = tid; idx < 128 * 64; idx += 256) {
                const int r = idx >> 6, j = idx & 63;
                const int gr = mloc + r;
                const int bb = gr >> 11, t = gr & 2047;
                const float inv = powf(10000.f, -(float)j * (1.f / 64.f));
                float s, cc;
                sincosf((float)t * inv, &s, &cc);
                const float x1 = stg[r * 132 + j];
                const float x2 = stg[r * 132 + j + 64];
                const float y1 = x1 * cc - x2 * s;
                const float y2 = x2 * cc + x1 * s;
                const size_t base = (((size_t)(bb * H_ + hsel) * T_ + t) << 7);
                __half h, l;
                split2h(y1, h, l); Oh[base + j] = h;      Ol[base + j] = l;
                split2h(y2, h, l); Oh[base + j + 64] = h; Ol[base + j + 64] = l;
            }
        }
    }
}

// ---------------- A_bar softmax + CAM bernoulli -> g_ve ----------------
__device__ __forceinline__ uint32_t rotl32(uint32_t x, int r) { return (x << r) | (x >> (32 - r)); }

__global__ void __launch_bounds__(256) abar_cam()
{
    const int bh = blockIdx.x;
    __shared__ float qrow[128];
    __shared__ float sc[2048];
    __shared__ float red[256];
    __shared__ float maskf;
    const int tid = threadIdx.x;

    const size_t qoff = ((size_t)bh * T_ + (T_ - 1)) * 128;
    if (tid < 128)
        qrow[tid] = __half2float(g_Qh[qoff + tid]) + __half2float(g_Ql[qoff + tid]);
    __syncthreads();

    for (int k = tid; k < 2048; k += 256) {
        const size_t koff = ((size_t)bh * T_ + k) * 128;
        const __half2* kh = (const __half2*)(g_Kh + koff);
        const __half2* kl = (const __half2*)(g_Kl + koff);
        float s = 0.f;
#pragma unroll
        for (int i = 0; i < 64; i++) {
            const float2 a = __half22float2(kh[i]);
            const float2 b = __half22float2(kl[i]);
            s = fmaf(a.x + b.x, qrow[2 * i], s);
            s = fmaf(a.y + b.y, qrow[2 * i + 1], s);
        }
        sc[k] = s * 0.08838834764831845f;
    }
    __syncthreads();

    float m = -FLT_MAX;
    for (int k = tid; k < 2048; k += 256) m = fmaxf(m, sc[k]);
    red[tid] = m; __syncthreads();
    for (int o = 128; o > 0; o >>= 1) { if (tid < o) red[tid] = fmaxf(red[tid], red[tid + o]); __syncthreads(); }
    const float gm = red[0];
    __syncthreads();

    float sum = 0.f;
    for (int k = tid; k < 2048; k += 256) { const float p = expf(sc[k] - gm); sc[k] = p; sum += p; }
    red[tid] = sum; __syncthreads();
    for (int o = 128; o > 0; o >>= 1) { if (tid < o) red[tid] += red[tid + o]; __syncthreads(); }
    const float invs = 1.f / red[0];
    __syncthreads();

    for (int k = tid; k < 2048; k += 256) sc[k] *= invs;
    __syncthreads();

    float ws = 0.f;
    for (int k = 1536 + tid; k < 2048; k += 256) ws += sc[k];
    red[tid] = ws; __syncthreads();
    for (int o = 128; o > 0; o >>= 1) { if (tid < o) red[tid] += red[tid + o]; __syncthreads(); }

    if (tid == 0) {
        const float avg = fmaxf(red[0] * (1.f / 512.f), 1e-6f);
        float p = fminf(fmaxf(sc[1535] / avg, 0.f), 1.f);
        uint32_t x0 = 0u, x1 = (uint32_t)bh;
        const uint32_t k0 = 0u, k1 = 42u, k2 = 0x1BD11BDAu ^ k0 ^ k1;
        x0 += k0; x1 += k1;
#define TF4(a,b,c,d)  x0+=x1; x1=rotl32(x1,a); x1^=x0; \
                      x0+=x1; x1=rotl32(x1,b); x1^=x0; \
                      x0+=x1; x1=rotl32(x1,c); x1^=x0; \
                      x0+=x1; x1=rotl32(x1,d); x1^=x0;
        TF4(13,15,26,6)   x0 += k1; x1 += k2 + 1u;
        TF4(17,29,16,24)  x0 += k2; x1 += k0 + 2u;
        TF4(13,15,26,6)   x0 += k0; x1 += k1 + 3u;
        TF4(17,29,16,24)  x0 += k1; x1 += k2 + 4u;
        TF4(13,15,26,6)   x0 += k2; x1 += k0 + 5u;
#undef TF4
        const uint32_t bits = x0 ^ x1;
        float uu = __uint_as_float((bits >> 9) | 0x3f800000u) - 1.0f;
        uu = fmaxf(uu, 0.f);
        maskf = (uu < p) ? 1.f : 0.f;
    }
    __syncthreads();

    if (tid < 128)
        g_ve[bh * 128 + tid] = g_v1535[bh * 128 + tid] * maskf * (1.f / 512.f);
}

// CAM window update in-place on fp16 Vt
__global__ void vt_update()
{
    const int idx = blockIdx.x * blockDim.x + threadIdx.x;
    const int bh = idx >> 15;
    const int rem = idx & 32767;
    const int d = rem >> 8;
    const int kk = rem & 255;
    const float ve = g_ve[bh * 128 + d];
    __half2* p = (__half2*)(g_Vth + ((size_t)(bh * 128 + d)) * 2048 + 1536) + kk;
    float2 x = __half22float2(*p);
    *p = __floats2half2_rn(x.x + ve, x.y + ve);
}

// ---------------- fused flash attention: Q in regs, triple-buffered K+V, 1 sync/iter ----------------
// smem: 3 buffers x (K 32KB + V 32KB) = 192KB. Q staged through buffer 2's K area.
#define FL_BUF   65536
#define FL_SMEM  (3 * FL_BUF)

__global__ void __launch_bounds__(256) flash_mma()
{
    extern __shared__ char smem[];
    const uint32_t sb = smem_u32(smem);
    const int tid = threadIdx.x, wid = tid >> 5, lane = tid & 31;
    const int bh = blockIdx.y;
    const int qb = 15 - blockIdx.x;
    const int nkt = qb + 1;

    const int c = tid >> 7, r = tid & 127;

    auto stageQ = [&]() {
        const char* sp = (const char*)(g_Qh + ((size_t)(bh * 2048 + qb * 128 + r)) * 128 + c * 64);
        const uint32_t drow = sb + 2 * FL_BUF + c * 16384 + r * 128;
#pragma unroll
        for (int g = 0; g < 8; g++) cp_async16(drow + ((g ^ (r & 7)) << 4), sp + g * 16);
    };
    auto loadKV = [&](int j, int s) {
        const char* spk = (const char*)(g_Kh + ((size_t)(bh * 2048 + j * 128 + r)) * 128 + c * 64);
        const uint32_t drk = sb + s * FL_BUF + c * 16384 + r * 128;
#pragma unroll
        for (int g = 0; g < 8; g++) cp_async16(drk + ((g ^ (r & 7)) << 4), spk + g * 16);
        const char* spv = (const char*)(g_Vth + ((size_t)(bh * 128 + r)) * 2048 + j * 128 + c * 64);
        const uint32_t drv = sb + s * FL_BUF + 32768 + c * 16384 + r * 128;
#pragma unroll
        for (int g = 0; g < 8; g++) cp_async16(drv + ((g ^ (r & 7)) << 4), spv + g * 16);
    };

    stageQ(); CP_COMMIT();
    loadKV(0, 0); CP_COMMIT();
    if (nkt > 1) { loadKV(1, 1); }
    CP_COMMIT();                      // group exists even if empty

    const int lr = lane & 15;
    const int rloc = (lane >> 2);
    const int colloc = (lane & 3) * 2;

    // Q fragments -> registers (once)
    uint32_t qfrag[8][4];
    CP_WAIT(2);
    __syncthreads();
#pragma unroll
    for (int ks = 0; ks < 8; ks++) {
        const int chunk = ks >> 2;
        const int g = (ks & 3) * 2 + (lane >> 4);
        const int ar = wid * 16 + lr;
        const uint32_t aoff = ar * 128 + ((g ^ (ar & 7)) << 4);
        LDSM_X4(qfrag[ks], sb + 2 * FL_BUF + chunk * 16384 + aoff);
    }

    float oacc[16][4];
#pragma unroll
    for (int nt = 0; nt < 16; nt++)
#pragma unroll
        for (int e = 0; e < 4; e++) oacc[nt][e] = 0.f;
    float m0 = -1e30f, m1 = -1e30f, l0 = 0.f, l1 = 0.f;
    uint32_t pfrag[8][4];

    const float scale = 0.08838834764831845f;

    for (int j = 0; j < nkt; j++) {
        const int s = j % 3;
        CP_WAIT(1);
        __syncthreads();     // buffers (j) ready for all; all warps done reading buffer (j+2)%3 (and qfrag at j=0)
        if (j + 2 < nkt) { loadKV(j + 2, (j + 2) % 3); CP_COMMIT(); }

        float sacc[16][4];
#pragma unroll
        for (int nt = 0; nt < 16; nt++)
#pragma unroll
            for (int e = 0; e < 4; e++) sacc[nt][e] = 0.f;

        const uint32_t kst = sb + s * FL_BUF;
#pragma unroll
        for (int ks = 0; ks < 8; ks++) {
            const int chunk = ks >> 2;
            const int g = (ks & 3) * 2 + (lane >> 4);
#pragma unroll
            for (int np = 0; np < 8; np++) {
                const int br = np * 16 + lr;
                const uint32_t boff = br * 128 + ((g ^ (br & 7)) << 4);
                uint32_t t4[4];
                LDSM_X4(t4, kst + chunk * 16384 + boff);
                uint32_t b0[2] = { t4[0], t4[2] };
                uint32_t b1[2] = { t4[1], t4[3] };
                mma16816_fp(sacc[2*np],   qfrag[ks], b0);
                mma16816_fp(sacc[2*np+1], qfrag[ks], b1);
            }
        }

        const bool diag = (j == qb);
        const int rg0 = wid * 16 + rloc;
#pragma unroll
        for (int nt = 0; nt < 16; nt++) {
            float* sx = sacc[nt];
            sx[0] *= scale; sx[1] *= scale; sx[2] *= scale; sx[3] *= scale;
            if (diag) {
                const int cl = nt * 8 + colloc;
                if (cl     > rg0)     sx[0] = -1e30f;
                if (cl + 1 > rg0)     sx[1] = -1e30f;
                if (cl     > rg0 + 8) sx[2] = -1e30f;
                if (cl + 1 > rg0 + 8) sx[3] = -1e30f;
            }
        }

        float mx0 = -1e30f, mx1 = -1e30f;
#pragma unroll
        for (int nt = 0; nt < 16; nt++) {
            mx0 = fmaxf(mx0, fmaxf(sacc[nt][0], sacc[nt][1]));
            mx1 = fmaxf(mx1, fmaxf(sacc[nt][2], sacc[nt][3]));
        }
        mx0 = fmaxf(mx0, __shfl_xor_sync(0xffffffffu, mx0, 1));
        mx0 = fmaxf(mx0, __shfl_xor_sync(0xffffffffu, mx0, 2));
        mx1 = fmaxf(mx1, __shfl_xor_sync(0xffffffffu, mx1, 1));
        mx1 = fmaxf(mx1, __shfl_xor_sync(0xffffffffu, mx1, 2));
        const float mn0 = fmaxf(m0, mx0), mn1 = fmaxf(m1, mx1);
        const float cr0 = __expf(m0 - mn0), cr1 = __expf(m1 - mn1);
        l0 *= cr0; l1 *= cr1; m0 = mn0; m1 = mn1;
#pragma unroll
        for (int nt = 0; nt < 16; nt++) {
            oacc[nt][0] *= cr0; oacc[nt][1] *= cr0;
            oacc[nt][2] *= cr1; oacc[nt][3] *= cr1;
        }
        float ps0 = 0.f, ps1 = 0.f;
#pragma unroll
        for (int kb = 0; kb < 8; kb++) {
            const float p00 = __expf(sacc[2*kb][0]   - mn0), p01 = __expf(sacc[2*kb][1]   - mn0);
            const float p02 = __expf(sacc[2*kb][2]   - mn1), p03 = __expf(sacc[2*kb][3]   - mn1);
            const float p10 = __expf(sacc[2*kb+1][0] - mn0), p11 = __expf(sacc[2*kb+1][1] - mn0);
            const float p12 = __expf(sacc[2*kb+1][2] - mn1), p13 = __expf(sacc[2*kb+1][3] - mn1);
            pfrag[kb][0] = packh2(p00, p01);
            pfrag[kb][1] = packh2(p02, p03);
            pfrag[kb][2] = packh2(p10, p11);
            pfrag[kb][3] = packh2(p12, p13);
            ps0 += p00 + p01 + p10 + p11;
            ps1 += p02 + p03 + p12 + p13;
        }
        ps0 += __shfl_xor_sync(0xffffffffu, ps0, 1);
        ps0 += __shfl_xor_sync(0xffffffffu, ps0, 2);
        ps1 += __shfl_xor_sync(0xffffffffu, ps1, 1);
        ps1 += __shfl_xor_sync(0xffffffffu, ps1, 2);
        l0 += ps0; l1 += ps1;

        const uint32_t vst = sb + s * FL_BUF + 32768;
#pragma unroll
        for (int kb = 0; kb < 8; kb++) {
            const int chunk = kb >> 2;
            const int g = (kb & 3) * 2 + (lane >> 4);
#pragma unroll
            for (int np = 0; np < 8; np++) {
                const int br = np * 16 + lr;
                const uint32_t boff = br * 128 + ((g ^ (br & 7)) << 4);
                uint32_t t4[4];
                LDSM_X4(t4, vst + chunk * 16384 + boff);
                uint32_t b0[2] = { t4[0], t4[2] };
                uint32_t b1[2] = { t4[1], t4[3] };
                mma16816_fp(oacc[2*np],   pfrag[kb], b0);
                mma16816_fp(oacc[2*np+1], pfrag[kb], b1);
            }
        }
    }

    // ---- writeout: fp16 AO ----
    const float inv0 = 1.f / l0, inv1 = 1.f / l1;
    const int bb = bh >> 4, hh = bh & 15;
    const int rgg0 = qb * 128 + wid * 16 + rloc;
    const size_t base0 = ((size_t)(bb * 2048 + rgg0)) * 2048 + hh * 128;
    const size_t base1 = base0 + (size_t)8 * 2048;
#pragma unroll
    for (int nt = 0; nt < 16; nt++) {
        const int d = nt * 8 + colloc;
        *(__half2*)(g_AOfh + base0 + d) = __floats2half2_rn(oacc[nt][0] * inv0, oacc[nt][1] * inv0);
        *(__half2*)(g_AOfh + base1 + d) = __floats2half2_rn(oacc[nt][2] * inv1, oacc[nt][3] * inv1);
    }
}

// ---------------- launch ----------------
extern "C" void kernel_launch(void* const* d_in, const int* in_sizes, int n_in,
                              void* d_out, int out_size)
{
    (void)in_sizes; (void)n_in; (void)out_size;
    const float* hidden = (const float*)d_in[0];
    const float* q_w = (const float*)d_in[2];
    const float* k_w = (const float*)d_in[3];
    const float* v_w = (const float*)d_in[4];
    const float* o_w = (const float*)d_in[5];
    float* out = (float*)d_out;

    cudaFuncSetAttribute(gemm_mma<1>, cudaFuncAttributeMaxDynamicSharedMemorySize, GT_SMEM);
    cudaFuncSetAttribute(gemm_mma<0>, cudaFuncAttributeMaxDynamicSharedMemorySize, GT_SMEM);
    cudaFuncSetAttribute(flash_mma, cudaFuncAttributeMaxDynamicSharedMemorySize, FL_SMEM);

    convert_all<<<dim3(8192, 5), 256>>>(hidden, q_w, k_w, v_w, o_w);
    gemm_mma<1><<<dim3(48, 32), 256, GT_SMEM>>>(nullptr);
    abar_cam<<<32, 256>>>();
    vt_update<<<4096, 256>>>();
    flash_mma<<<dim3(16, 32), 256, FL_SMEM>>>();
    gemm_mma<0><<<dim3(16, 32), 256, GT_SMEM>>>(out);
}

// round 17
// speedup vs baseline: 1.0416x; 1.0288x over previous
#include <cuda_runtime.h>
#include <cuda_bf16.h>
#include <cuda_fp16.h>
#include <math.h>
#include <stdint.h>
#include <float.h>

#define B_  2
#define T_  2048
#define HID_ 2048
#define H_  16
#define D_  128
#define BH_ (B_*H_)
#define BT_ (B_*T_)

// ---------------- device scratch ----------------
__device__ float g_ve[BH_ * D_];
__device__ float g_v1535[BH_ * D_];
__device__ float g_sc[BH_ * T_];                 // abar scores
__device__ __align__(8) float2 g_ropecs[T_ * 64]; // rope cos/sin table

// fp16 operands
__device__ __align__(16) __half g_Hfh[(size_t)BT_ * HID_];
__device__ __align__(16) __half g_Wfh[3][(size_t)HID_ * HID_];
__device__ __align__(16) __half g_OWfh[(size_t)HID_ * HID_];
__device__ __align__(16) __half g_AOfh[(size_t)BT_ * HID_];
__device__ __align__(16) __half g_Qh[(size_t)BH_ * T_ * D_];
__device__ __align__(16) __half g_Ql[(size_t)BH_ * T_ * D_];
__device__ __align__(16) __half g_Kh[(size_t)BH_ * T_ * D_];
__device__ __align__(16) __half g_Kl[(size_t)BH_ * T_ * D_];
__device__ __align__(16) __half g_Vth[(size_t)BH_ * D_ * T_];

// ---------------- PTX helpers (compute_103-safe) ----------------
__device__ __forceinline__ uint32_t smem_u32(const void* p) {
    uint32_t a;
    asm("{ .reg .u64 t; cvta.to.shared.u64 t, %1; cvt.u32.u64 %0, t; }" : "=r"(a) : "l"(p));
    return a;
}
__device__ __forceinline__ void cp_async16(uint32_t dst, const void* src) {
    asm volatile("cp.async.cg.shared.global [%0], [%1], 16;" :: "r"(dst), "l"(src));
}
#define CP_COMMIT() asm volatile("cp.async.commit_group;" ::: "memory")
#define CP_WAIT(N)  asm volatile("cp.async.wait_group %0;" :: "n"(N) : "memory")

#define LDSM_X4(r, addr) \
    asm volatile("ldmatrix.sync.aligned.m8n8.x4.shared.b16 {%0,%1,%2,%3}, [%4];" \
        : "=r"((r)[0]), "=r"((r)[1]), "=r"((r)[2]), "=r"((r)[3]) : "r"(addr))

__device__ __forceinline__ void mma16816_fp(float* c, const uint32_t* a, const uint32_t* b) {
    asm volatile("mma.sync.aligned.m16n8k16.row.col.f32.f16.f16.f32 "
        "{%0,%1,%2,%3}, {%4,%5,%6,%7}, {%8,%9}, {%0,%1,%2,%3};"
        : "+f"(c[0]), "+f"(c[1]), "+f"(c[2]), "+f"(c[3])
        : "r"(a[0]), "r"(a[1]), "r"(a[2]), "r"(a[3]), "r"(b[0]), "r"(b[1]));
}

__device__ __forceinline__ void split2h(float x, __half& h, __half& l) {
    h = __float2half_rn(x);
    l = __float2half_rn(x - __half2float(h));
}
__device__ __forceinline__ uint32_t packh2(float a, float b) {
    __half2 h = __floats2half2_rn(a, b);
    return *reinterpret_cast<uint32_t*>(&h);
}

// ---------------- rope table (same expressions as before -> bit-identical) ----------------
__global__ void rope_tab()
{
    const int idx = blockIdx.x * blockDim.x + threadIdx.x;   // 131072
    const int t = idx >> 6, j = idx & 63;
    const float inv = powf(10000.f, -(float)j * (1.f / 64.f));
    float s, cc;
    sincosf((float)t * inv, &s, &cc);
    g_ropecs[idx] = make_float2(cc, s);
}

// ---------------- input conversions ----------------
__global__ void convert_all(const float* __restrict__ hs,
                            const float* __restrict__ qw, const float* __restrict__ kw,
                            const float* __restrict__ vw, const float* __restrict__ ow)
{
    const int sel = blockIdx.y;
    if (sel > 0 && blockIdx.x >= 4096) return;
    const size_t i = ((size_t)blockIdx.x * blockDim.x + threadIdx.x) * 4;
    const float* s = (sel == 0) ? hs : (sel == 1) ? qw : (sel == 2) ? kw : (sel == 3) ? vw : ow;
    __half* dst = (sel == 0) ? g_Hfh : (sel == 4) ? g_OWfh : g_Wfh[sel - 1];
    const float4 v = *(const float4*)(s + i);
    *(__half2*)(dst + i)     = __floats2half2_rn(v.x, v.y);
    *(__half2*)(dst + i + 2) = __floats2half2_rn(v.z, v.w);
}

// ---------------- mma.sync fp16 GEMM, 3-stage pipeline, 2 CTAs/SM ----------------
#define GT_TILE  16384
#define GT_STAGE (2 * GT_TILE)
#define GT_SMEM  (3 * GT_STAGE)

template<int MODE>
__global__ void __launch_bounds__(256, 2) gemm_mma(float* __restrict__ C)
{
    extern __shared__ char smem[];
    const uint32_t sbase = smem_u32(smem);
    const int tid = threadIdx.x;
    const int wid = tid >> 5;
    const int lane = tid & 31;

    int wsel = 0, hsel = 0, mloc, nloc;
    if (MODE == 1) {
        wsel = blockIdx.x >> 4;
        hsel = blockIdx.x & 15;
        mloc = blockIdx.y * 128; nloc = hsel * 128;
    } else {
        mloc = blockIdx.y * 128; nloc = blockIdx.x * 128;
    }

    const int part = tid >> 7;
    const int u = tid & 127;
    const char* gsrc;
    if (MODE == 1) gsrc = (part == 0) ? (const char*)g_Hfh : (const char*)g_Wfh[wsel];
    else           gsrc = (part == 0) ? (const char*)g_AOfh : (const char*)g_OWfh;
    const int growbase = (part == 0) ? mloc : nloc;
    const uint32_t tpart = sbase + part * GT_TILE;

    auto load_stage = [&](int c, int s) {
        const int r = u;
        const char* src = gsrc + ((size_t)(growbase + r) * 2048 + c * 64) * 2;
        const uint32_t drow = tpart + s * GT_STAGE + r * 128;
#pragma unroll
        for (int g = 0; g < 8; g++)
            cp_async16(drow + (((g ^ (r & 7)) << 4)), src + g * 16);
    };

    const int wm = wid & 3;
    const int wn = wid >> 2;

    float acc[2][8][4];
#pragma unroll
    for (int a = 0; a < 2; a++)
#pragma unroll
        for (int b = 0; b < 8; b++)
#pragma unroll
            for (int cx = 0; cx < 4; cx++) acc[a][b][cx] = 0.f;

    load_stage(0, 0); CP_COMMIT();
    load_stage(1, 1); CP_COMMIT();

    for (int c = 0; c < 32; ++c) {
        if (c < 31) { CP_WAIT(1); } else { CP_WAIT(0); }
        __syncthreads();
        if (c + 2 < 32) { load_stage(c + 2, (c + 2) % 3); CP_COMMIT(); }

        const uint32_t st = sbase + (c % 3) * GT_STAGE;
#pragma unroll
        for (int ks = 0; ks < 4; ks++) {
            const int lr = lane & 15;
            const int g = ks * 2 + (lane >> 4);

            uint32_t ah[2][4];
#pragma unroll
            for (int mb = 0; mb < 2; mb++) {
                const int r = wm * 32 + mb * 16 + lr;
                const uint32_t off = r * 128 + (((g ^ (r & 7)) << 4));
                LDSM_X4(ah[mb], st + off);
            }
            uint32_t bhf[8][2];
#pragma unroll
            for (int np = 0; np < 4; np++) {
                const int r = wn * 64 + np * 16 + lr;
                const uint32_t off = r * 128 + (((g ^ (r & 7)) << 4));
                uint32_t t4[4];
                LDSM_X4(t4, st + GT_TILE + off);
                bhf[2*np][0] = t4[0]; bhf[2*np][1] = t4[2];
                bhf[2*np+1][0] = t4[1]; bhf[2*np+1][1] = t4[3];
            }
#pragma unroll
            for (int mb = 0; mb < 2; mb++)
#pragma unroll
                for (int nb = 0; nb < 8; nb++)
                    mma16816_fp(acc[mb][nb], ah[mb], bhf[nb]);
        }
    }

    if (MODE == 0) {
#pragma unroll
        for (int mb = 0; mb < 2; mb++)
#pragma unroll
            for (int rh = 0; rh < 2; rh++) {
                const int row = wm * 32 + mb * 16 + rh * 8 + (lane >> 2);
                float* dst = C + (size_t)(mloc + row) * 2048 + nloc;
                const int cbase = wn * 64 + (lane & 3) * 2;
#pragma unroll
                for (int nb = 0; nb < 8; nb++)
                    *(float2*)(dst + cbase + nb * 8) =
                        make_float2(acc[mb][nb][rh * 2], acc[mb][nb][rh * 2 + 1]);
            }
    } else {
        __syncthreads();
        float* stg = (float*)smem;     // [128][132]
#pragma unroll
        for (int mb = 0; mb < 2; mb++)
#pragma unroll
            for (int rh = 0; rh < 2; rh++) {
                const int row = wm * 32 + mb * 16 + rh * 8 + (lane >> 2);
                const int cbase = wn * 64 + (lane & 3) * 2;
#pragma unroll
                for (int nb = 0; nb < 8; nb++) {
                    stg[row * 132 + cbase + nb * 8]     = acc[mb][nb][rh * 2];
                    stg[row * 132 + cbase + nb * 8 + 1] = acc[mb][nb][rh * 2 + 1];
                }
            }
        __syncthreads();

        if (wsel == 2) {
            for (int idx = tid; idx < 128 * 128; idx += 256) {
                const int d = idx >> 7, r = idx & 127;
                const int gr = mloc + r;
                const int bb = gr >> 11, t = gr & 2047;
                const float x = stg[r * 132 + d];
                g_Vth[((size_t)((bb * H_ + hsel) * D_ + d)) * T_ + t] = __float2half_rn(x);
                if (t == 1535) g_v1535[(bb * H_ + hsel) * 128 + d] = x;
            }
        } else {
            __half* Oh = (wsel == 0) ? g_Qh : g_Kh;
            __half* Ol = (wsel == 0) ? g_Ql : g_Kl;
            for (int idx = tid; idx < 128 * 64; idx += 256) {
                const int r = idx >> 6, j = idx & 63;
                const int gr = mloc + r;
                const int bb = gr >> 11, t = gr & 2047;
                const float2 cs = g_ropecs[t * 64 + j];
                const float x1 = stg[r * 132 + j];
                const float x2 = stg[r * 132 + j + 64];
                const float y1 = x1 * cs.x - x2 * cs.y;
                const float y2 = x2 * cs.x + x1 * cs.y;
                const size_t base = (((size_t)(bb * H_ + hsel) * T_ + t) << 7);
                __half h, l;
                split2h(y1, h, l); Oh[base + j] = h;      Ol[base + j] = l;
                split2h(y2, h, l); Oh[base + j + 64] = h; Ol[base + j + 64] = l;
            }
        }
    }
}

// ---------------- abar pass 1: last-row QK scores (256 blocks) ----------------
__global__ void __launch_bounds__(256) abar_dot()
{
    const int bh = blockIdx.y;
    const int k = blockIdx.x * 256 + threadIdx.x;
    __shared__ float qrow[128];
    const int tid = threadIdx.x;

    const size_t qoff = ((size_t)bh * T_ + (T_ - 1)) * 128;
    if (tid < 128)
        qrow[tid] = __half2float(g_Qh[qoff + tid]) + __half2float(g_Ql[qoff + tid]);
    __syncthreads();

    const size_t koff = ((size_t)bh * T_ + k) * 128;
    const __half2* kh = (const __half2*)(g_Kh + koff);
    const __half2* kl = (const __half2*)(g_Kl + koff);
    float s = 0.f;
#pragma unroll
    for (int i = 0; i < 64; i++) {
        const float2 a = __half22float2(kh[i]);
        const float2 b = __half22float2(kl[i]);
        s = fmaf(a.x + b.x, qrow[2 * i], s);
        s = fmaf(a.y + b.y, qrow[2 * i + 1], s);
    }
    g_sc[bh * 2048 + k] = s * 0.08838834764831845f;
}

// ---------------- abar pass 2: softmax + CAM bernoulli -> g_ve (reduction order identical) ----------------
__device__ __forceinline__ uint32_t rotl32(uint32_t x, int r) { return (x << r) | (x >> (32 - r)); }

__global__ void __launch_bounds__(256) abar_mask()
{
    const int bh = blockIdx.x;
    __shared__ float sc[2048];
    __shared__ float red[256];
    __shared__ float maskf;
    const int tid = threadIdx.x;

    for (int k = tid; k < 2048; k += 256) sc[k] = g_sc[bh * 2048 + k];
    __syncthreads();

    float m = -FLT_MAX;
    for (int k = tid; k < 2048; k += 256) m = fmaxf(m, sc[k]);
    red[tid] = m; __syncthreads();
    for (int o = 128; o > 0; o >>= 1) { if (tid < o) red[tid] = fmaxf(red[tid], red[tid + o]); __syncthreads(); }
    const float gm = red[0];
    __syncthreads();

    float sum = 0.f;
    for (int k = tid; k < 2048; k += 256) { const float p = expf(sc[k] - gm); sc[k] = p; sum += p; }
    red[tid] = sum; __syncthreads();
    for (int o = 128; o > 0; o >>= 1) { if (tid < o) red[tid] += red[tid + o]; __syncthreads(); }
    const float invs = 1.f / red[0];
    __syncthreads();

    for (int k = tid; k < 2048; k += 256) sc[k] *= invs;
    __syncthreads();

    float ws = 0.f;
    for (int k = 1536 + tid; k < 2048; k += 256) ws += sc[k];
    red[tid] = ws; __syncthreads();
    for (int o = 128; o > 0; o >>= 1) { if (tid < o) red[tid] += red[tid + o]; __syncthreads(); }

    if (tid == 0) {
        const float avg = fmaxf(red[0] * (1.f / 512.f), 1e-6f);
        float p = fminf(fmaxf(sc[1535] / avg, 0.f), 1.f);
        uint32_t x0 = 0u, x1 = (uint32_t)bh;
        const uint32_t k0 = 0u, k1 = 42u, k2 = 0x1BD11BDAu ^ k0 ^ k1;
        x0 += k0; x1 += k1;
#define TF4(a,b,c,d)  x0+=x1; x1=rotl32(x1,a); x1^=x0; \
                      x0+=x1; x1=rotl32(x1,b); x1^=x0; \
                      x0+=x1; x1=rotl32(x1,c); x1^=x0; \
                      x0+=x1; x1=rotl32(x1,d); x1^=x0;
        TF4(13,15,26,6)   x0 += k1; x1 += k2 + 1u;
        TF4(17,29,16,24)  x0 += k2; x1 += k0 + 2u;
        TF4(13,15,26,6)   x0 += k0; x1 += k1 + 3u;
        TF4(17,29,16,24)  x0 += k1; x1 += k2 + 4u;
        TF4(13,15,26,6)   x0 += k2; x1 += k0 + 5u;
#undef TF4
        const uint32_t bits = x0 ^ x1;
        float uu = __uint_as_float((bits >> 9) | 0x3f800000u) - 1.0f;
        uu = fmaxf(uu, 0.f);
        maskf = (uu < p) ? 1.f : 0.f;
    }
    __syncthreads();

    if (tid < 128)
        g_ve[bh * 128 + tid] = g_v1535[bh * 128 + tid] * maskf * (1.f / 512.f);
}

// CAM window update in-place on fp16 Vt
__global__ void vt_update()
{
    const int idx = blockIdx.x * blockDim.x + threadIdx.x;
    const int bh = idx >> 15;
    const int rem = idx & 32767;
    const int d = rem >> 8;
    const int kk = rem & 255;
    const float ve = g_ve[bh * 128 + d];
    __half2* p = (__half2*)(g_Vth + ((size_t)(bh * 128 + d)) * 2048 + 1536) + kk;
    float2 x = __half22float2(*p);
    *p = __floats2half2_rn(x.x + ve, x.y + ve);
}

// ---------------- fused flash attention (R16 layout: Q regs, triple-buffered K+V) ----------------
#define FL_BUF   65536
#define FL_SMEM  (3 * FL_BUF)

__global__ void __launch_bounds__(256) flash_mma()
{
    extern __shared__ char smem[];
    const uint32_t sb = smem_u32(smem);
    const int tid = threadIdx.x, wid = tid >> 5, lane = tid & 31;
    const int bh = blockIdx.y;
    const int qb = 15 - blockIdx.x;
    const int nkt = qb + 1;

    const int c = tid >> 7, r = tid & 127;

    auto stageQ = [&]() {
        const char* sp = (const char*)(g_Qh + ((size_t)(bh * 2048 + qb * 128 + r)) * 128 + c * 64);
        const uint32_t drow = sb + 2 * FL_BUF + c * 16384 + r * 128;
#pragma unroll
        for (int g = 0; g < 8; g++) cp_async16(drow + ((g ^ (r & 7)) << 4), sp + g * 16);
    };
    auto loadKV = [&](int j, int s) {
        const char* spk = (const char*)(g_Kh + ((size_t)(bh * 2048 + j * 128 + r)) * 128 + c * 64);
        const uint32_t drk = sb + s * FL_BUF + c * 16384 + r * 128;
#pragma unroll
        for (int g = 0; g < 8; g++) cp_async16(drk + ((g ^ (r & 7)) << 4), spk + g * 16);
        const char* spv = (const char*)(g_Vth + ((size_t)(bh * 128 + r)) * 2048 + j * 128 + c * 64);
        const uint32_t drv = sb + s * FL_BUF + 32768 + c * 16384 + r * 128;
#pragma unroll
        for (int g = 0; g < 8; g++) cp_async16(drv + ((g ^ (r & 7)) << 4), spv + g * 16);
    };

    stageQ(); CP_COMMIT();
    loadKV(0, 0); CP_COMMIT();
    if (nkt > 1) { loadKV(1, 1); }
    CP_COMMIT();

    const int lr = lane & 15;
    const int rloc = (lane >> 2);
    const int colloc = (lane & 3) * 2;

    uint32_t qfrag[8][4];
    CP_WAIT(2);
    __syncthreads();
#pragma unroll
    for (int ks = 0; ks < 8; ks++) {
        const int chunk = ks >> 2;
        const int g = (ks & 3) * 2 + (lane >> 4);
        const int ar = wid * 16 + lr;
        const uint32_t aoff = ar * 128 + ((g ^ (ar & 7)) << 4);
        LDSM_X4(qfrag[ks], sb + 2 * FL_BUF + chunk * 16384 + aoff);
    }

    float oacc[16][4];
#pragma unroll
    for (int nt = 0; nt < 16; nt++)
#pragma unroll
        for (int e = 0; e < 4; e++) oacc[nt][e] = 0.f;
    float m0 = -1e30f, m1 = -1e30f, l0 = 0.f, l1 = 0.f;
    uint32_t pfrag[8][4];

    const float scale = 0.08838834764831845f;

    for (int j = 0; j < nkt; j++) {
        const int s = j % 3;
        CP_WAIT(1);
        __syncthreads();
        if (j + 2 < nkt) { loadKV(j + 2, (j + 2) % 3); CP_COMMIT(); }

        float sacc[16][4];
#pragma unroll
        for (int nt = 0; nt < 16; nt++)
#pragma unroll
            for (int e = 0; e < 4; e++) sacc[nt][e] = 0.f;

        const uint32_t kst = sb + s * FL_BUF;
#pragma unroll
        for (int ks = 0; ks < 8; ks++) {
            const int chunk = ks >> 2;
            const int g = (ks & 3) * 2 + (lane >> 4);
#pragma unroll
            for (int np = 0; np < 8; np++) {
                const int br = np * 16 + lr;
                const uint32_t boff = br * 128 + ((g ^ (br & 7)) << 4);
                uint32_t t4[4];
                LDSM_X4(t4, kst + chunk * 16384 + boff);
                uint32_t b0[2] = { t4[0], t4[2] };
                uint32_t b1[2] = { t4[1], t4[3] };
                mma16816_fp(sacc[2*np],   qfrag[ks], b0);
                mma16816_fp(sacc[2*np+1], qfrag[ks], b1);
            }
        }

        const bool diag = (j == qb);
        const int rg0 = wid * 16 + rloc;
#pragma unroll
        for (int nt = 0; nt < 16; nt++) {
            float* sx = sacc[nt];
            sx[0] *= scale; sx[1] *= scale; sx[2] *= scale; sx[3] *= scale;
            if (diag) {
                const int cl = nt * 8 + colloc;
                if (cl     > rg0)     sx[0] = -1e30f;
                if (cl + 1 > rg0)     sx[1] = -1e30f;
                if (cl     > rg0 + 8) sx[2] = -1e30f;
                if (cl + 1 > rg0 + 8) sx[3] = -1e30f;
            }
        }

        float mx0 = -1e30f, mx1 = -1e30f;
#pragma unroll
        for (int nt = 0; nt < 16; nt++) {
            mx0 = fmaxf(mx0, fmaxf(sacc[nt][0], sacc[nt][1]));
            mx1 = fmaxf(mx1, fmaxf(sacc[nt][2], sacc[nt][3]));
        }
        mx0 = fmaxf(mx0, __shfl_xor_sync(0xffffffffu, mx0, 1));
        mx0 = fmaxf(mx0, __shfl_xor_sync(0xffffffffu, mx0, 2));
        mx1 = fmaxf(mx1, __shfl_xor_sync(0xffffffffu, mx1, 1));
        mx1 = fmaxf(mx1, __shfl_xor_sync(0xffffffffu, mx1, 2));
        const float mn0 = fmaxf(m0, mx0), mn1 = fmaxf(m1, mx1);
        const float cr0 = __expf(m0 - mn0), cr1 = __expf(m1 - mn1);
        l0 *= cr0; l1 *= cr1; m0 = mn0; m1 = mn1;
#pragma unroll
        for (int nt = 0; nt < 16; nt++) {
            oacc[nt][0] *= cr0; oacc[nt][1] *= cr0;
            oacc[nt][2] *= cr1; oacc[nt][3] *= cr1;
        }
        float ps0 = 0.f, ps1 = 0.f;
#pragma unroll
        for (int kb = 0; kb < 8; kb++) {
            const float p00 = __expf(sacc[2*kb][0]   - mn0), p01 = __expf(sacc[2*kb][1]   - mn0);
            const float p02 = __expf(sacc[2*kb][2]   - mn1), p03 = __expf(sacc[2*kb][3]   - mn1);
            const float p10 = __expf(sacc[2*kb+1][0] - mn0), p11 = __expf(sacc[2*kb+1][1] - mn0);
            const float p12 = __expf(sacc[2*kb+1][2] - mn1), p13 = __expf(sacc[2*kb+1][3] - mn1);
            pfrag[kb][0] = packh2(p00, p01);
            pfrag[kb][1] = packh2(p02, p03);
            pfrag[kb][2] = packh2(p10, p11);
            pfrag[kb][3] = packh2(p12, p13);
            ps0 += p00 + p01 + p10 + p11;
            ps1 += p02 + p03 + p12 + p13;
        }
        ps0 += __shfl_xor_sync(0xffffffffu, ps0, 1);
        ps0 += __shfl_xor_sync(0xffffffffu, ps0, 2);
        ps1 += __shfl_xor_sync(0xffffffffu, ps1, 1);
        ps1 += __shfl_xor_sync(0xffffffffu, ps1, 2);
        l0 += ps0; l1 += ps1;

        const uint32_t vst = sb + s * FL_BUF + 32768;
#pragma unroll
        for (int kb = 0; kb < 8; kb++) {
            const int chunk = kb >> 2;
            const int g = (kb & 3) * 2 + (lane >> 4);
#pragma unroll
            for (int np = 0; np < 8; np++) {
                const int br = np * 16 + lr;
                const uint32_t boff = br * 128 + ((g ^ (br & 7)) << 4);
                uint32_t t4[4];
                LDSM_X4(t4, vst + chunk * 16384 + boff);
                uint32_t b0[2] = { t4[0], t4[2] };
                uint32_t b1[2] = { t4[1], t4[3] };
                mma16816_fp(oacc[2*np],   pfrag[kb], b0);
                mma16816_fp(oacc[2*np+1], pfrag[kb], b1);
            }
        }
    }

    const float inv0 = 1.f / l0, inv1 = 1.f / l1;
    const int bb = bh >> 4, hh = bh & 15;
    const int rgg0 = qb * 128 + wid * 16 + rloc;
    const size_t base0 = ((size_t)(bb * 2048 + rgg0)) * 2048 + hh * 128;
    const size_t base1 = base0 + (size_t)8 * 2048;
#pragma unroll
    for (int nt = 0; nt < 16; nt++) {
        const int d = nt * 8 + colloc;
        *(__half2*)(g_AOfh + base0 + d) = __floats2half2_rn(oacc[nt][0] * inv0, oacc[nt][1] * inv0);
        *(__half2*)(g_AOfh + base1 + d) = __floats2half2_rn(oacc[nt][2] * inv1, oacc[nt][3] * inv1);
    }
}

// ---------------- launch ----------------
extern "C" void kernel_launch(void* const* d_in, const int* in_sizes, int n_in,
                              void* d_out, int out_size)
{
    (void)in_sizes; (void)n_in; (void)out_size;
    const float* hidden = (const float*)d_in[0];
    const float* q_w = (const float*)d_in[2];
    const float* k_w = (const float*)d_in[3];
    const float* v_w = (const float*)d_in[4];
    const float* o_w = (const float*)d_in[5];
    float* out = (float*)d_out;

    cudaFuncSetAttribute(gemm_mma<1>, cudaFuncAttributeMaxDynamicSharedMemorySize, GT_SMEM);
    cudaFuncSetAttribute(gemm_mma<0>, cudaFuncAttributeMaxDynamicSharedMemorySize, GT_SMEM);
    cudaFuncSetAttribute(flash_mma, cudaFuncAttributeMaxDynamicSharedMemorySize, FL_SMEM);

    rope_tab<<<512, 256>>>();
    convert_all<<<dim3(8192, 5), 256>>>(hidden, q_w, k_w, v_w, o_w);
    gemm_mma<1><<<dim3(48, 32), 256, GT_SMEM>>>(nullptr);
    abar_dot<<<dim3(8, 32), 256>>>();
    abar_mask<<<32, 256>>>();
    vt_update<<<4096, 256>>>();
    flash_mma<<<dim3(16, 32), 256, FL_SMEM>>>();
    gemm_mma<0><<<dim3(16, 32), 256, GT_SMEM>>>(out);
}